// round 14
// baseline (speedup 1.0000x reference)
#include <cuda_runtime.h>
#include <cuda_fp16.h>
#include <math.h>

#define NN 50000
#define EE 1600000
#define RCHUNK 32

// ---------------- scratch ----------------
__device__ __align__(16) __half2 g_xl_h[NN * 32];
__device__ __align__(16) __half2 g_xg_h[NN * 32];
__device__ __align__(16) float g_gat[NN * 64];
__device__ __align__(16) float g_gcn[NN * 64];
__device__ __align__(16) float g_node4[NN * 4];    // {cx, cy, nind, asrc}
__device__ __align__(16) float g_nodeD[NN * 4];    // {cx, cy, adst, 0}
__device__ float g_exself[NN];
__device__ float g_den[NN];
__device__ float g_deg[NN];
__device__ float g_dis[NN];
__device__ int   g_cnt[NN];
__device__ int   g_startx[NN + 1];
__device__ int   g_cursor[NN];
__device__ int   g_bsum[64];
__device__ int   g_boff[64];
__device__ __align__(8) uint2 g_edata8[EE];  // {src, half2(ex,ew)} binned by dst

// ---------------- helpers ----------------
__device__ __forceinline__ void red4(float* p, float a, float b, float c, float d) {
    asm volatile("red.global.add.v4.f32 [%0], {%1,%2,%3,%4};"
                 :: "l"(p), "f"(a), "f"(b), "f"(c), "f"(d) : "memory");
}
__device__ __forceinline__ void red1(float* p, float v) {
    asm volatile("red.global.add.f32 [%0], %1;" :: "l"(p), "f"(v) : "memory");
}
__device__ __forceinline__ float elu1(float v) { return v > 0.f ? v : (expf(v) - 1.f); }

#define MMA16816(ac, a, b)                                                        \
    asm volatile(                                                                 \
        "mma.sync.aligned.m16n8k16.row.col.f32.f16.f16.f32 "                      \
        "{%0,%1,%2,%3}, {%4,%5,%6,%7}, {%8,%9}, {%0,%1,%2,%3};"                   \
        : "+f"((ac)[0]), "+f"((ac)[1]), "+f"((ac)[2]), "+f"((ac)[3])              \
        : "r"((a)[0]), "r"((a)[1]), "r"((a)[2]), "r"((a)[3]),                     \
          "r"((b)[0]), "r"((b)[1]))

// ---------------- merged tensor-core GEMM (both branches in one grid) -----------
// blockIdx.y = 0: x_local@gat_w + attention epilogue; = 1: x_global@gcn_w.
#define XS 136
__global__ void k_gemm(const float* __restrict__ X0, const float* __restrict__ W0,
                       __half2* __restrict__ O0,
                       const float* __restrict__ X1, const float* __restrict__ W1,
                       __half2* __restrict__ O1,
                       const float* __restrict__ att_s, const float* __restrict__ att_d,
                       int nrows) {
    extern __shared__ __half smh[];
    __half* Xh = smh;
    __half* Xl = smh + 128 * XS;
    __half* Wh = smh + 256 * XS;
    __half* Wl = smh + 256 * XS + 64 * XS;
    __shared__ float s_as[64], s_ad[64];
    bool do_att = (blockIdx.y == 0);
    const float* X = do_att ? X0 : X1;
    const float* W = do_att ? W0 : W1;
    __half2* outh = do_att ? O0 : O1;
    int tid = threadIdx.x;
    int r0 = blockIdx.x * 128;
    if (do_att) {
        if (tid < 64) s_as[tid] = att_s[tid];
        else if (tid < 128) s_ad[tid - 64] = att_d[tid - 64];
    }
    // load X -> Xh/Xl (paired conversions)
    {
        int r = tid & 127, kb = (tid >> 7) * 64;
        int rr = r0 + r;
        const float4* src = (const float4*)(X + (size_t)rr * 128 + kb);
#pragma unroll
        for (int j = 0; j < 16; j++) {
            float4 v = (rr < nrows) ? src[j] : make_float4(0.f, 0.f, 0.f, 0.f);
            int k = kb + 4 * j;
            __half2 h01 = __floats2half2_rn(v.x, v.y);
            __half2 h23 = __floats2half2_rn(v.z, v.w);
            float2 b01 = __half22float2(h01);
            float2 b23 = __half22float2(h23);
            *(__half2*)&Xh[r * XS + k]     = h01;
            *(__half2*)&Xh[r * XS + k + 2] = h23;
            *(__half2*)&Xl[r * XS + k]     = __floats2half2_rn(v.x - b01.x, v.y - b01.y);
            *(__half2*)&Xl[r * XS + k + 2] = __floats2half2_rn(v.z - b23.x, v.w - b23.y);
        }
    }
    // load W -> Wh/Wl
    {
        int h = tid & 63, kb = (tid >> 6) * 32;
        const float4* src = (const float4*)(W + (size_t)h * 128 + kb);
#pragma unroll
        for (int j = 0; j < 8; j++) {
            float4 v = src[j];
            int k = kb + 4 * j;
            __half2 h01 = __floats2half2_rn(v.x, v.y);
            __half2 h23 = __floats2half2_rn(v.z, v.w);
            float2 b01 = __half22float2(h01);
            float2 b23 = __half22float2(h23);
            *(__half2*)&Wh[h * XS + k]     = h01;
            *(__half2*)&Wh[h * XS + k + 2] = h23;
            *(__half2*)&Wl[h * XS + k]     = __floats2half2_rn(v.x - b01.x, v.y - b01.y);
            *(__half2*)&Wl[h * XS + k + 2] = __floats2half2_rn(v.z - b23.x, v.w - b23.y);
        }
    }
    __syncthreads();

    int wid = tid >> 5, lane = tid & 31;
    int m0 = wid * 16;
    int g = lane >> 2, c = (lane & 3) * 2;
    float acc[8][4] = {};

#pragma unroll
    for (int kk = 0; kk < 128; kk += 16) {
        unsigned ah[4], al[4];
        ah[0] = *(const unsigned*)&Xh[(m0 + g) * XS + kk + c];
        ah[1] = *(const unsigned*)&Xh[(m0 + g + 8) * XS + kk + c];
        ah[2] = *(const unsigned*)&Xh[(m0 + g) * XS + kk + c + 8];
        ah[3] = *(const unsigned*)&Xh[(m0 + g + 8) * XS + kk + c + 8];
        al[0] = *(const unsigned*)&Xl[(m0 + g) * XS + kk + c];
        al[1] = *(const unsigned*)&Xl[(m0 + g + 8) * XS + kk + c];
        al[2] = *(const unsigned*)&Xl[(m0 + g) * XS + kk + c + 8];
        al[3] = *(const unsigned*)&Xl[(m0 + g + 8) * XS + kk + c + 8];
#pragma unroll
        for (int nt = 0; nt < 8; nt++) {
            int n = nt * 8 + g;
            unsigned bh[2], bl[2];
            bh[0] = *(const unsigned*)&Wh[n * XS + kk + c];
            bh[1] = *(const unsigned*)&Wh[n * XS + kk + c + 8];
            bl[0] = *(const unsigned*)&Wl[n * XS + kk + c];
            bl[1] = *(const unsigned*)&Wl[n * XS + kk + c + 8];
            MMA16816(acc[nt], ah, bh);
            MMA16816(acc[nt], al, bh);
            MMA16816(acc[nt], ah, bl);
        }
    }

    int ra = r0 + m0 + g, rb = ra + 8;
    __half* oh = (__half*)outh;
#pragma unroll
    for (int nt = 0; nt < 8; nt++) {
        int cb = nt * 8 + c;
        if (ra < nrows)
            *(__half2*)&oh[(size_t)ra * 64 + cb] = __floats2half2_rn(acc[nt][0], acc[nt][1]);
        if (rb < nrows)
            *(__half2*)&oh[(size_t)rb * 64 + cb] = __floats2half2_rn(acc[nt][2], acc[nt][3]);
    }

    if (do_att) {
        float pa_s = 0.f, pa_d = 0.f, pb_s = 0.f, pb_d = 0.f;
#pragma unroll
        for (int nt = 0; nt < 8; nt++) {
            int cb = nt * 8 + c;
            pa_s += acc[nt][0] * s_as[cb] + acc[nt][1] * s_as[cb + 1];
            pa_d += acc[nt][0] * s_ad[cb] + acc[nt][1] * s_ad[cb + 1];
            pb_s += acc[nt][2] * s_as[cb] + acc[nt][3] * s_as[cb + 1];
            pb_d += acc[nt][2] * s_ad[cb] + acc[nt][3] * s_ad[cb + 1];
        }
        pa_s += __shfl_down_sync(~0u, pa_s, 2, 4); pa_s += __shfl_down_sync(~0u, pa_s, 1, 4);
        pa_d += __shfl_down_sync(~0u, pa_d, 2, 4); pa_d += __shfl_down_sync(~0u, pa_d, 1, 4);
        pb_s += __shfl_down_sync(~0u, pb_s, 2, 4); pb_s += __shfl_down_sync(~0u, pb_s, 1, 4);
        pb_d += __shfl_down_sync(~0u, pb_d, 2, 4); pb_d += __shfl_down_sync(~0u, pb_d, 1, 4);
        if ((lane & 3) == 0) {
            if (ra < nrows) {
                g_node4[4 * ra + 3] = pa_s;
                g_nodeD[4 * ra + 2] = pa_d;
                float e = pa_s + pa_d;
                e = e > 0.f ? e : 0.2f * e;
                float ex = expf(e);
                g_exself[ra] = ex; g_den[ra] = ex; g_deg[ra] = 1.f;
            }
            if (rb < nrows) {
                g_node4[4 * rb + 3] = pb_s;
                g_nodeD[4 * rb + 2] = pb_d;
                float e = pb_s + pb_d;
                e = e > 0.f ? e : 0.2f * e;
                float ex = expf(e);
                g_exself[rb] = ex; g_den[rb] = ex; g_deg[rb] = 1.f;
            }
        }
    }
}

// ---------------- per-node noise MLP + coord packing ----------------
__global__ void k_nind(const float* __restrict__ nf, const float* __restrict__ coord,
                       const float* __restrict__ fc1w, const float* __restrict__ fc1b,
                       const float* __restrict__ fc2w, const float* __restrict__ fc2b) {
    __shared__ float w1[100], b1[10], w2[10], b2s;
    int tid = threadIdx.x;
    if (tid < 100) w1[tid] = fc1w[tid];
    if (tid < 10) { b1[tid] = fc1b[tid]; w2[tid] = fc2w[tid]; }
    if (tid == 0) b2s = fc2b[0];
    __syncthreads();
    int i = blockIdx.x * blockDim.x + tid;
    if (i >= NN) return;
    float x[10];
#pragma unroll
    for (int k = 0; k < 10; k++) x[k] = nf[i * 10 + k];
    float acc = b2s;
#pragma unroll
    for (int j = 0; j < 10; j++) {
        float h = b1[j];
#pragma unroll
        for (int k = 0; k < 10; k++) h += x[k] * w1[j * 10 + k];
        acc += elu1(h) * w2[j];
    }
    float2 c = ((const float2*)coord)[i];
    *(float4*)&g_node4[4 * i] = make_float4(c.x, c.y, acc, 0.f);
    *(float4*)&g_nodeD[4 * i] = make_float4(c.x, c.y, 0.f, 0.f);
}

// ---------------- histogram over dst ----------------
__global__ void k_hist(const int* __restrict__ ei) {
    int t = blockIdx.x * blockDim.x + threadIdx.x;
    if (t < EE) atomicAdd(&g_cnt[ei[EE + t]], 1);
}

// ---------------- 3-kernel exclusive scan ----------------
__global__ void k_scan1() {
    __shared__ int wsum[8], woff[8];
    int tid = threadIdx.x, lane = tid & 31, wrp = tid >> 5;
    int base = blockIdx.x * 1024 + tid * 4;
    int c0 = 0, c1 = 0, c2 = 0, c3 = 0;
    if (base + 0 < NN) c0 = g_cnt[base + 0];
    if (base + 1 < NN) c1 = g_cnt[base + 1];
    if (base + 2 < NN) c2 = g_cnt[base + 2];
    if (base + 3 < NN) c3 = g_cnt[base + 3];
    int tot = c0 + c1 + c2 + c3;
    int v = tot;
#pragma unroll
    for (int off = 1; off < 32; off <<= 1) {
        int o = __shfl_up_sync(~0u, v, off);
        if (lane >= off) v += o;
    }
    if (lane == 31) wsum[wrp] = v;
    __syncthreads();
    if (wrp == 0 && lane < 8) {
        int w = wsum[lane], iv = w;
#pragma unroll
        for (int off = 1; off < 8; off <<= 1) {
            int o = __shfl_up_sync(0xffu, iv, off);
            if (lane >= off) iv += o;
        }
        woff[lane] = iv - w;
    }
    __syncthreads();
    int excl = (v - tot) + woff[wrp];
    if (base + 0 < NN) g_startx[base + 0] = excl;
    if (base + 1 < NN) g_startx[base + 1] = excl + c0;
    if (base + 2 < NN) g_startx[base + 2] = excl + c0 + c1;
    if (base + 3 < NN) g_startx[base + 3] = excl + c0 + c1 + c2;
    if (tid == 255) g_bsum[blockIdx.x] = excl + tot;
}
__global__ void k_scan2(int nblk) {
    int run = 0;
    for (int i = 0; i < nblk; i++) { g_boff[i] = run; run += g_bsum[i]; }
    g_startx[NN] = EE;
}
__global__ void k_scan3() {
    int i = blockIdx.x * blockDim.x + threadIdx.x;
    if (i >= NN) return;
    int s = g_startx[i] + g_boff[i >> 10];
    g_startx[i] = s;
    g_cursor[i] = s;
}

// ---------------- bin pass ----------------
__global__ void k_bin(const int* __restrict__ ei) {
    int t = blockIdx.x * blockDim.x + threadIdx.x;
    if (t >= EE) return;
    int s = ei[t], d = ei[EE + t];
    float4 ns = *(const float4*)&g_node4[4 * s];
    float4 nd = *(const float4*)&g_nodeD[4 * d];
    float dx = ns.x - nd.x, dy = ns.y - nd.y;
    float gw = expf(-(dx * dx + dy * dy) * (1.0f / 1800.0f));
    float z = gw * (1.f + ns.z) - 1.f;
    float w = 0.1f + 1.9f / (1.f + expf(-z));
    bool m = (w >= 0.2f);
    float e = ns.w + nd.z;
    e = e > 0.f ? e : 0.2f * e;
    float ex = expf(e);
    __half2 p = m ? __floats2half2_rn(ex, w) : __floats2half2_rn(0.f, 0.f);
    if (m) atomicAdd(&g_deg[d], w);
    int pos = atomicAdd(&g_cursor[d], 1);
    unsigned int pb = *reinterpret_cast<unsigned int*>(&p);
    g_edata8[pos] = make_uint2((unsigned int)s, pb);
}

// ---------------- dis = rsqrt(deg) ----------------
__global__ void k_dis() {
    int i = blockIdx.x * blockDim.x + threadIdx.x;
    if (i < NN) g_dis[i] = rsqrtf(g_deg[i]);
}

// ---------------- sorted-run reduce: 16 threads/group, both branches per lane ----
__global__ void k_reduce() {
    int gid = (blockIdx.x * blockDim.x + threadIdx.x) >> 4;
    int l = threadIdx.x & 15;
    int beg = gid * RCHUNK;
    if (beg >= EE) return;
    int end = min(beg + RCHUNK, EE);
    int lo = 0, hi = NN - 1;
    while (lo < hi) {
        int mid = (lo + hi + 1) >> 1;
        if (g_startx[mid] <= beg) lo = mid; else hi = mid - 1;
    }
    int n = lo;
    int nxt = g_startx[n + 1];
    float4 ag = make_float4(0.f, 0.f, 0.f, 0.f);
    float4 ac = make_float4(0.f, 0.f, 0.f, 0.f);
    float den = 0.f;
    bool dirty = false;
    uint2 rec = g_edata8[beg];
    for (int i = beg; i < end; i++) {
        uint2 cur = rec;
        if (i + 1 < end) rec = g_edata8[i + 1];
        while (i >= nxt) {
            if (dirty) {
                red4(&g_gat[(size_t)n * 64 + 4 * l], ag.x, ag.y, ag.z, ag.w);
                red4(&g_gcn[(size_t)n * 64 + 4 * l], ac.x, ac.y, ac.z, ac.w);
                if (l == 0) red1(&g_den[n], den);
                ag = make_float4(0.f, 0.f, 0.f, 0.f);
                ac = make_float4(0.f, 0.f, 0.f, 0.f);
                den = 0.f;
                dirty = false;
            }
            n++;
            nxt = g_startx[n + 1];
        }
        __half2 p; *reinterpret_cast<unsigned int*>(&p) = cur.y;
        float2 exw = __half22float2(p);
        if (exw.x == 0.f && exw.y == 0.f) continue;
        int s = (int)cur.x;
        float diss = __ldg(&g_dis[s]);
        float ewd = exw.y * diss;
        const __half2* pl = &g_xl_h[(size_t)s * 32 + 2 * l];
        float2 f0 = __half22float2(pl[0]), f1 = __half22float2(pl[1]);
        ag.x += exw.x * f0.x; ag.y += exw.x * f0.y;
        ag.z += exw.x * f1.x; ag.w += exw.x * f1.y;
        const __half2* pg = &g_xg_h[(size_t)s * 32 + 2 * l];
        float2 u0 = __half22float2(pg[0]), u1 = __half22float2(pg[1]);
        ac.x += ewd * u0.x; ac.y += ewd * u0.y;
        ac.z += ewd * u1.x; ac.w += ewd * u1.y;
        den += exw.x;
        dirty = true;
    }
    if (dirty) {
        red4(&g_gat[(size_t)n * 64 + 4 * l], ag.x, ag.y, ag.z, ag.w);
        red4(&g_gcn[(size_t)n * 64 + 4 * l], ac.x, ac.y, ac.z, ac.w);
        if (l == 0) red1(&g_den[n], den);
    }
}

// ---------------- fusion (K-split x2): finalize both branches inline -------------
__global__ void __launch_bounds__(256, 4)
k_fusion(const float* __restrict__ W1, const float* __restrict__ b1,
         const float* __restrict__ w2, const float* __restrict__ b2,
         const float* __restrict__ gat_b, const float* __restrict__ gcn_b,
         float* __restrict__ out, int nrows) {
    extern __shared__ float sm[];
    float (*Xs)[132] = (float(*)[132])sm;
    float (*Ws)[68]  = (float(*)[68])(sm + 64 * 132);
    int tid = threadIdx.x;
    int r0 = blockIdx.x * 128;
    int ty = tid >> 4, tx = tid & 15;
    int n0 = ty * 8, h0 = tx * 4;
    float acc[8][4] = {};

#pragma unroll
    for (int p = 0; p < 2; p++) {
        if (p) __syncthreads();
        {
            int h = tid & 63, kq = (tid >> 6) * 16;
            const float4* src = (const float4*)(W1 + (size_t)h * 128 + p * 64 + kq);
#pragma unroll
            for (int j = 0; j < 4; j++) {
                float4 v = src[j];
                int k = kq + 4 * j;
                Ws[k + 0][h] = v.x; Ws[k + 1][h] = v.y;
                Ws[k + 2][h] = v.z; Ws[k + 3][h] = v.w;
            }
        }
        {
            int r = tid & 127, ko = (tid >> 7) * 32;
            int rr = r0 + r;
            if (rr < nrows) {
                if (p == 0) {
                    float inv = 1.f / g_den[rr];
                    float exs = g_exself[rr];
                    const float4*  pa = (const float4*)(g_gat + (size_t)rr * 64) + (ko >> 2);
                    const __half2* px = &g_xl_h[(size_t)rr * 32 + (ko >> 1)];
                    const float4*  pb = (const float4*)gat_b + (ko >> 2);
#pragma unroll
                    for (int j = 0; j < 8; j++) {
                        float4 a = pa[j], b = pb[j];
                        float2 x0 = __half22float2(px[2 * j]);
                        float2 x1 = __half22float2(px[2 * j + 1]);
                        int k = ko + 4 * j;
                        Xs[k + 0][r] = elu1((a.x + exs * x0.x) * inv + b.x);
                        Xs[k + 1][r] = elu1((a.y + exs * x0.y) * inv + b.y);
                        Xs[k + 2][r] = elu1((a.z + exs * x1.x) * inv + b.z);
                        Xs[k + 3][r] = elu1((a.w + exs * x1.y) * inv + b.w);
                    }
                } else {
                    float dis = g_dis[rr];
                    const float4*  pa = (const float4*)(g_gcn + (size_t)rr * 64) + (ko >> 2);
                    const __half2* px = &g_xg_h[(size_t)rr * 32 + (ko >> 1)];
                    const float4*  pb = (const float4*)gcn_b + (ko >> 2);
#pragma unroll
                    for (int j = 0; j < 8; j++) {
                        float4 a = pa[j], b = pb[j];
                        float2 x0 = __half22float2(px[2 * j]);
                        float2 x1 = __half22float2(px[2 * j + 1]);
                        int k = ko + 4 * j;
                        Xs[k + 0][r] = fmaxf(dis * (a.x + dis * x0.x) + b.x, 0.f);
                        Xs[k + 1][r] = fmaxf(dis * (a.y + dis * x0.y) + b.y, 0.f);
                        Xs[k + 2][r] = fmaxf(dis * (a.z + dis * x1.x) + b.z, 0.f);
                        Xs[k + 3][r] = fmaxf(dis * (a.w + dis * x1.y) + b.w, 0.f);
                    }
                }
            } else {
#pragma unroll
                for (int j = 0; j < 32; j++) Xs[ko + j][r] = 0.f;
            }
        }
        __syncthreads();
#pragma unroll 4
        for (int k = 0; k < 64; k++) {
            float4 x0 = *(const float4*)&Xs[k][n0];
            float4 x1 = *(const float4*)&Xs[k][n0 + 4];
            float4 wv = *(const float4*)&Ws[k][h0];
            float xs[8] = {x0.x, x0.y, x0.z, x0.w, x1.x, x1.y, x1.z, x1.w};
            float ws[4] = {wv.x, wv.y, wv.z, wv.w};
#pragma unroll
            for (int i = 0; i < 8; i++)
#pragma unroll
                for (int j = 0; j < 4; j++) acc[i][j] += xs[i] * ws[j];
        }
    }

    float b1v[4], w2v[4];
#pragma unroll
    for (int j = 0; j < 4; j++) { b1v[j] = b1[h0 + j]; w2v[j] = w2[h0 + j]; }
    float part[8];
#pragma unroll
    for (int i = 0; i < 8; i++) {
        float p = 0.f;
#pragma unroll
        for (int j = 0; j < 4; j++) p += fmaxf(acc[i][j] + b1v[j], 0.f) * w2v[j];
        part[i] = p;
    }
#pragma unroll
    for (int off = 8; off >= 1; off >>= 1)
#pragma unroll
        for (int i = 0; i < 8; i++) part[i] += __shfl_down_sync(0xffffffffu, part[i], off, 16);
    if (tx == 0) {
        float bb = b2[0];
#pragma unroll
        for (int i = 0; i < 8; i++) {
            int r = r0 + n0 + i;
            if (r < nrows) out[r] = part[i] + bb;
        }
    }
}

// ---------------- launch (stream-forked DAG; handles destroyed before return) ----
extern "C" void kernel_launch(void* const* d_in, const int* in_sizes, int n_in,
                              void* d_out, int out_size) {
    const float* x_local  = (const float*)d_in[0];
    const float* x_global = (const float*)d_in[1];
    const float* nf       = (const float*)d_in[2];
    const float* coord    = (const float*)d_in[3];
    const int*   ei       = (const int*)d_in[4];
    const float* fc1w     = (const float*)d_in[5];
    const float* fc1b     = (const float*)d_in[6];
    const float* fc2w     = (const float*)d_in[7];
    const float* fc2b     = (const float*)d_in[8];
    const float* gat_w    = (const float*)d_in[9];
    const float* att_s    = (const float*)d_in[10];
    const float* att_d    = (const float*)d_in[11];
    const float* gat_b    = (const float*)d_in[12];
    const float* gcn_w    = (const float*)d_in[13];
    const float* gcn_b    = (const float*)d_in[14];
    const float* fus_w1   = (const float*)d_in[15];
    const float* fus_b1   = (const float*)d_in[16];
    const float* fus_w2   = (const float*)d_in[17];
    const float* fus_b2   = (const float*)d_in[18];
    float* out = (float*)d_out;

    const int SMEM_MMA = (256 * XS + 128 * XS) * (int)sizeof(__half);  // 104448
    const int SMEM_F   = (64 * 132 + 64 * 68) * (int)sizeof(float);    // 51200
    cudaFuncSetAttribute(k_gemm,   cudaFuncAttributeMaxDynamicSharedMemorySize, SMEM_MMA);
    cudaFuncSetAttribute(k_fusion, cudaFuncAttributeMaxDynamicSharedMemorySize, SMEM_F);

    float *pgat, *pgcn;
    __half2 *pxlh, *pxgh;
    void *pcnt;
    cudaGetSymbolAddress((void**)&pxlh, g_xl_h);
    cudaGetSymbolAddress((void**)&pxgh, g_xg_h);
    cudaGetSymbolAddress((void**)&pgat, g_gat);
    cudaGetSymbolAddress((void**)&pgcn, g_gcn);
    cudaGetSymbolAddress(&pcnt, g_cnt);

    const int NB_N   = (NN + 255) / 256;                 // 196
    const int NB_E   = (EE + 255) / 256;                 // 6250
    const int NB_G   = (NN + 127) / 128;                 // 391
    const int NSCAN  = (NN + 1023) / 1024;               // 49
    const int NGROUP = (EE + RCHUNK - 1) / RCHUNK;       // 50000
    const int NB_R   = (NGROUP * 16 + 255) / 256;        // 3125

    cudaStream_t s1, s2;
    cudaStreamCreateWithFlags(&s1, cudaStreamNonBlocking);
    cudaStreamCreateWithFlags(&s2, cudaStreamNonBlocking);
    cudaEvent_t evRoot, evScan, evMset;
    cudaEventCreateWithFlags(&evRoot, cudaEventDisableTiming);
    cudaEventCreateWithFlags(&evScan, cudaEventDisableTiming);
    cudaEventCreateWithFlags(&evMset, cudaEventDisableTiming);

    cudaEventRecord(evRoot, 0);

    // branch s1: histogram + scan chain
    cudaStreamWaitEvent(s1, evRoot, 0);
    cudaMemsetAsync(pcnt, 0, NN * sizeof(int), s1);
    k_hist<<<NB_E, 256, 0, s1>>>(ei);
    k_scan1<<<NSCAN, 256, 0, s1>>>();
    k_scan2<<<1, 1, 0, s1>>>(NSCAN);
    k_scan3<<<NB_N, 256, 0, s1>>>();
    cudaEventRecord(evScan, s1);

    // branch s2: accumulator memsets
    cudaStreamWaitEvent(s2, evRoot, 0);
    cudaMemsetAsync(pgat, 0, (size_t)NN * 64 * sizeof(float), s2);
    cudaMemsetAsync(pgcn, 0, (size_t)NN * 64 * sizeof(float), s2);
    cudaEventRecord(evMset, s2);

    // main stream: node MLP + merged GEMM
    k_nind<<<NB_N, 256>>>(nf, coord, fc1w, fc1b, fc2w, fc2b);
    k_gemm<<<dim3(NB_G, 2), 256, SMEM_MMA>>>(x_local, gat_w, pxlh,
                                             x_global, gcn_w, pxgh,
                                             att_s, att_d, NN);

    // join: bin needs scan + nind + gemm; reduce additionally needs memsets
    cudaStreamWaitEvent(0, evScan, 0);
    k_bin<<<NB_E, 256>>>(ei);
    k_dis<<<NB_N, 256>>>();
    cudaStreamWaitEvent(0, evMset, 0);
    k_reduce<<<NB_R, 256>>>();
    k_fusion<<<NB_G, 256, SMEM_F>>>(fus_w1, fus_b1, fus_w2, fus_b2, gat_b, gcn_b, out, NN);

    cudaStreamDestroy(s1);
    cudaStreamDestroy(s2);
    cudaEventDestroy(evRoot);
    cudaEventDestroy(evScan);
    cudaEventDestroy(evMset);
}

// round 15
// speedup vs baseline: 1.4659x; 1.4659x over previous
#include <cuda_runtime.h>
#include <cuda_fp16.h>
#include <math.h>

#define NN 50000
#define EE 1600000
#define RCHUNK 64

// ---------------- scratch ----------------
__device__ __align__(16) __half2 g_xl_h[NN * 32];
__device__ __align__(16) __half2 g_xg_h[NN * 32];
__device__ __align__(16) float g_gat[NN * 64];
__device__ __align__(16) float g_gcn[NN * 64];
__device__ __align__(16) float g_node4[NN * 4];    // {cx, cy, nind, asrc}
__device__ __align__(16) float g_nodeD[NN * 4];    // {cx, cy, adst, 0}
__device__ float g_exself[NN];
__device__ float g_den[NN];
__device__ float g_deg[NN];
__device__ float g_dis[NN];
__device__ int   g_cnt[NN];
__device__ int   g_startx[NN + 1];
__device__ int   g_rank[EE];      // per-edge rank within its dst bin (from hist)
__device__ int   g_bsum[64];
__device__ int   g_boff[64];
__device__ __align__(8) uint2 g_edata8[EE];  // {src, half2(ex,ew)} binned by dst

// ---------------- helpers ----------------
__device__ __forceinline__ void red4(float* p, float a, float b, float c, float d) {
    asm volatile("red.global.add.v4.f32 [%0], {%1,%2,%3,%4};"
                 :: "l"(p), "f"(a), "f"(b), "f"(c), "f"(d) : "memory");
}
__device__ __forceinline__ void red1(float* p, float v) {
    asm volatile("red.global.add.f32 [%0], %1;" :: "l"(p), "f"(v) : "memory");
}
__device__ __forceinline__ float elu1(float v) { return v > 0.f ? v : (expf(v) - 1.f); }

#define MMA16816(ac, a, b)                                                        \
    asm volatile(                                                                 \
        "mma.sync.aligned.m16n8k16.row.col.f32.f16.f16.f32 "                      \
        "{%0,%1,%2,%3}, {%4,%5,%6,%7}, {%8,%9}, {%0,%1,%2,%3};"                   \
        : "+f"((ac)[0]), "+f"((ac)[1]), "+f"((ac)[2]), "+f"((ac)[3])              \
        : "r"((a)[0]), "r"((a)[1]), "r"((a)[2]), "r"((a)[3]),                     \
          "r"((b)[0]), "r"((b)[1]))

// ---------------- merged tensor-core GEMM (both branches in one grid) -----------
// blockIdx.y = 0: x_local@gat_w + attention epilogue; = 1: x_global@gcn_w.
#define XS 136
__global__ void k_gemm(const float* __restrict__ X0, const float* __restrict__ W0,
                       __half2* __restrict__ O0,
                       const float* __restrict__ X1, const float* __restrict__ W1,
                       __half2* __restrict__ O1,
                       const float* __restrict__ att_s, const float* __restrict__ att_d,
                       int nrows) {
    extern __shared__ __half smh[];
    __half* Xh = smh;
    __half* Xl = smh + 128 * XS;
    __half* Wh = smh + 256 * XS;
    __half* Wl = smh + 256 * XS + 64 * XS;
    __shared__ float s_as[64], s_ad[64];
    bool do_att = (blockIdx.y == 0);
    const float* X = do_att ? X0 : X1;
    const float* W = do_att ? W0 : W1;
    __half2* outh = do_att ? O0 : O1;
    int tid = threadIdx.x;
    int r0 = blockIdx.x * 128;
    if (do_att) {
        if (tid < 64) s_as[tid] = att_s[tid];
        else if (tid < 128) s_ad[tid - 64] = att_d[tid - 64];
    }
    // load X -> Xh/Xl (paired conversions)
    {
        int r = tid & 127, kb = (tid >> 7) * 64;
        int rr = r0 + r;
        const float4* src = (const float4*)(X + (size_t)rr * 128 + kb);
#pragma unroll
        for (int j = 0; j < 16; j++) {
            float4 v = (rr < nrows) ? src[j] : make_float4(0.f, 0.f, 0.f, 0.f);
            int k = kb + 4 * j;
            __half2 h01 = __floats2half2_rn(v.x, v.y);
            __half2 h23 = __floats2half2_rn(v.z, v.w);
            float2 b01 = __half22float2(h01);
            float2 b23 = __half22float2(h23);
            *(__half2*)&Xh[r * XS + k]     = h01;
            *(__half2*)&Xh[r * XS + k + 2] = h23;
            *(__half2*)&Xl[r * XS + k]     = __floats2half2_rn(v.x - b01.x, v.y - b01.y);
            *(__half2*)&Xl[r * XS + k + 2] = __floats2half2_rn(v.z - b23.x, v.w - b23.y);
        }
    }
    // load W -> Wh/Wl
    {
        int h = tid & 63, kb = (tid >> 6) * 32;
        const float4* src = (const float4*)(W + (size_t)h * 128 + kb);
#pragma unroll
        for (int j = 0; j < 8; j++) {
            float4 v = src[j];
            int k = kb + 4 * j;
            __half2 h01 = __floats2half2_rn(v.x, v.y);
            __half2 h23 = __floats2half2_rn(v.z, v.w);
            float2 b01 = __half22float2(h01);
            float2 b23 = __half22float2(h23);
            *(__half2*)&Wh[h * XS + k]     = h01;
            *(__half2*)&Wh[h * XS + k + 2] = h23;
            *(__half2*)&Wl[h * XS + k]     = __floats2half2_rn(v.x - b01.x, v.y - b01.y);
            *(__half2*)&Wl[h * XS + k + 2] = __floats2half2_rn(v.z - b23.x, v.w - b23.y);
        }
    }
    __syncthreads();

    int wid = tid >> 5, lane = tid & 31;
    int m0 = wid * 16;
    int g = lane >> 2, c = (lane & 3) * 2;
    float acc[8][4] = {};

#pragma unroll
    for (int kk = 0; kk < 128; kk += 16) {
        unsigned ah[4], al[4];
        ah[0] = *(const unsigned*)&Xh[(m0 + g) * XS + kk + c];
        ah[1] = *(const unsigned*)&Xh[(m0 + g + 8) * XS + kk + c];
        ah[2] = *(const unsigned*)&Xh[(m0 + g) * XS + kk + c + 8];
        ah[3] = *(const unsigned*)&Xh[(m0 + g + 8) * XS + kk + c + 8];
        al[0] = *(const unsigned*)&Xl[(m0 + g) * XS + kk + c];
        al[1] = *(const unsigned*)&Xl[(m0 + g + 8) * XS + kk + c];
        al[2] = *(const unsigned*)&Xl[(m0 + g) * XS + kk + c + 8];
        al[3] = *(const unsigned*)&Xl[(m0 + g + 8) * XS + kk + c + 8];
#pragma unroll
        for (int nt = 0; nt < 8; nt++) {
            int n = nt * 8 + g;
            unsigned bh[2], bl[2];
            bh[0] = *(const unsigned*)&Wh[n * XS + kk + c];
            bh[1] = *(const unsigned*)&Wh[n * XS + kk + c + 8];
            bl[0] = *(const unsigned*)&Wl[n * XS + kk + c];
            bl[1] = *(const unsigned*)&Wl[n * XS + kk + c + 8];
            MMA16816(acc[nt], ah, bh);
            MMA16816(acc[nt], al, bh);
            MMA16816(acc[nt], ah, bl);
        }
    }

    int ra = r0 + m0 + g, rb = ra + 8;
    __half* oh = (__half*)outh;
#pragma unroll
    for (int nt = 0; nt < 8; nt++) {
        int cb = nt * 8 + c;
        if (ra < nrows)
            *(__half2*)&oh[(size_t)ra * 64 + cb] = __floats2half2_rn(acc[nt][0], acc[nt][1]);
        if (rb < nrows)
            *(__half2*)&oh[(size_t)rb * 64 + cb] = __floats2half2_rn(acc[nt][2], acc[nt][3]);
    }

    if (do_att) {
        float pa_s = 0.f, pa_d = 0.f, pb_s = 0.f, pb_d = 0.f;
#pragma unroll
        for (int nt = 0; nt < 8; nt++) {
            int cb = nt * 8 + c;
            pa_s += acc[nt][0] * s_as[cb] + acc[nt][1] * s_as[cb + 1];
            pa_d += acc[nt][0] * s_ad[cb] + acc[nt][1] * s_ad[cb + 1];
            pb_s += acc[nt][2] * s_as[cb] + acc[nt][3] * s_as[cb + 1];
            pb_d += acc[nt][2] * s_ad[cb] + acc[nt][3] * s_ad[cb + 1];
        }
        pa_s += __shfl_down_sync(~0u, pa_s, 2, 4); pa_s += __shfl_down_sync(~0u, pa_s, 1, 4);
        pa_d += __shfl_down_sync(~0u, pa_d, 2, 4); pa_d += __shfl_down_sync(~0u, pa_d, 1, 4);
        pb_s += __shfl_down_sync(~0u, pb_s, 2, 4); pb_s += __shfl_down_sync(~0u, pb_s, 1, 4);
        pb_d += __shfl_down_sync(~0u, pb_d, 2, 4); pb_d += __shfl_down_sync(~0u, pb_d, 1, 4);
        if ((lane & 3) == 0) {
            if (ra < nrows) {
                g_node4[4 * ra + 3] = pa_s;
                g_nodeD[4 * ra + 2] = pa_d;
                float e = pa_s + pa_d;
                e = e > 0.f ? e : 0.2f * e;
                float ex = expf(e);
                g_exself[ra] = ex; g_den[ra] = ex; g_deg[ra] = 1.f;
            }
            if (rb < nrows) {
                g_node4[4 * rb + 3] = pb_s;
                g_nodeD[4 * rb + 2] = pb_d;
                float e = pb_s + pb_d;
                e = e > 0.f ? e : 0.2f * e;
                float ex = expf(e);
                g_exself[rb] = ex; g_den[rb] = ex; g_deg[rb] = 1.f;
            }
        }
    }
}

// ---------------- per-node noise MLP + coord packing ----------------
__global__ void k_nind(const float* __restrict__ nf, const float* __restrict__ coord,
                       const float* __restrict__ fc1w, const float* __restrict__ fc1b,
                       const float* __restrict__ fc2w, const float* __restrict__ fc2b) {
    __shared__ float w1[100], b1[10], w2[10], b2s;
    int tid = threadIdx.x;
    if (tid < 100) w1[tid] = fc1w[tid];
    if (tid < 10) { b1[tid] = fc1b[tid]; w2[tid] = fc2w[tid]; }
    if (tid == 0) b2s = fc2b[0];
    __syncthreads();
    int i = blockIdx.x * blockDim.x + tid;
    if (i >= NN) return;
    float x[10];
#pragma unroll
    for (int k = 0; k < 10; k++) x[k] = nf[i * 10 + k];
    float acc = b2s;
#pragma unroll
    for (int j = 0; j < 10; j++) {
        float h = b1[j];
#pragma unroll
        for (int k = 0; k < 10; k++) h += x[k] * w1[j * 10 + k];
        acc += elu1(h) * w2[j];
    }
    float2 c = ((const float2*)coord)[i];
    *(float4*)&g_node4[4 * i] = make_float4(c.x, c.y, acc, 0.f);
    *(float4*)&g_nodeD[4 * i] = make_float4(c.x, c.y, 0.f, 0.f);
}

// ---------------- histogram over dst + per-edge rank ----------------
__global__ void k_hist(const int* __restrict__ ei) {
    int t = blockIdx.x * blockDim.x + threadIdx.x;
    if (t >= EE) return;
    int pos = atomicAdd(&g_cnt[ei[EE + t]], 1);
    g_rank[t] = pos;
}

// ---------------- 3-kernel exclusive scan ----------------
__global__ void k_scan1() {
    __shared__ int wsum[8], woff[8];
    int tid = threadIdx.x, lane = tid & 31, wrp = tid >> 5;
    int base = blockIdx.x * 1024 + tid * 4;
    int c0 = 0, c1 = 0, c2 = 0, c3 = 0;
    if (base + 0 < NN) c0 = g_cnt[base + 0];
    if (base + 1 < NN) c1 = g_cnt[base + 1];
    if (base + 2 < NN) c2 = g_cnt[base + 2];
    if (base + 3 < NN) c3 = g_cnt[base + 3];
    int tot = c0 + c1 + c2 + c3;
    int v = tot;
#pragma unroll
    for (int off = 1; off < 32; off <<= 1) {
        int o = __shfl_up_sync(~0u, v, off);
        if (lane >= off) v += o;
    }
    if (lane == 31) wsum[wrp] = v;
    __syncthreads();
    if (wrp == 0 && lane < 8) {
        int w = wsum[lane], iv = w;
#pragma unroll
        for (int off = 1; off < 8; off <<= 1) {
            int o = __shfl_up_sync(0xffu, iv, off);
            if (lane >= off) iv += o;
        }
        woff[lane] = iv - w;
    }
    __syncthreads();
    int excl = (v - tot) + woff[wrp];
    if (base + 0 < NN) g_startx[base + 0] = excl;
    if (base + 1 < NN) g_startx[base + 1] = excl + c0;
    if (base + 2 < NN) g_startx[base + 2] = excl + c0 + c1;
    if (base + 3 < NN) g_startx[base + 3] = excl + c0 + c1 + c2;
    if (tid == 255) g_bsum[blockIdx.x] = excl + tot;
}
__global__ void k_scan2(int nblk) {
    int run = 0;
    for (int i = 0; i < nblk; i++) { g_boff[i] = run; run += g_bsum[i]; }
    g_startx[NN] = EE;
}
__global__ void k_scan3() {
    int i = blockIdx.x * blockDim.x + threadIdx.x;
    if (i >= NN) return;
    g_startx[i] = g_startx[i] + g_boff[i >> 10];
}

// ---------------- bin pass: atomic-free record placement ----------------
__global__ void k_bin(const int* __restrict__ ei) {
    int t = blockIdx.x * blockDim.x + threadIdx.x;
    if (t >= EE) return;
    int s = ei[t], d = ei[EE + t];
    float4 ns = *(const float4*)&g_node4[4 * s];
    float4 nd = *(const float4*)&g_nodeD[4 * d];
    float dx = ns.x - nd.x, dy = ns.y - nd.y;
    float gw = expf(-(dx * dx + dy * dy) * (1.0f / 1800.0f));
    float z = gw * (1.f + ns.z) - 1.f;
    float w = 0.1f + 1.9f / (1.f + expf(-z));
    bool m = (w >= 0.2f);
    float e = ns.w + nd.z;
    e = e > 0.f ? e : 0.2f * e;
    float ex = expf(e);
    __half2 p = m ? __floats2half2_rn(ex, w) : __floats2half2_rn(0.f, 0.f);
    if (m) atomicAdd(&g_deg[d], w);
    int pos = __ldg(&g_startx[d]) + g_rank[t];
    unsigned int pb = *reinterpret_cast<unsigned int*>(&p);
    g_edata8[pos] = make_uint2((unsigned int)s, pb);
}

// ---------------- dis = rsqrt(deg) ----------------
__global__ void k_dis() {
    int i = blockIdx.x * blockDim.x + threadIdx.x;
    if (i < NN) g_dis[i] = rsqrtf(g_deg[i]);
}

// ---------------- sorted-run reduce: 16 threads/group, both branches per lane ----
__global__ void k_reduce() {
    int gid = (blockIdx.x * blockDim.x + threadIdx.x) >> 4;
    int l = threadIdx.x & 15;
    int beg = gid * RCHUNK;
    if (beg >= EE) return;
    int end = min(beg + RCHUNK, EE);
    int lo = 0, hi = NN - 1;
    while (lo < hi) {
        int mid = (lo + hi + 1) >> 1;
        if (g_startx[mid] <= beg) lo = mid; else hi = mid - 1;
    }
    int n = lo;
    int nxt = g_startx[n + 1];
    float4 ag = make_float4(0.f, 0.f, 0.f, 0.f);
    float4 ac = make_float4(0.f, 0.f, 0.f, 0.f);
    float den = 0.f;
    bool dirty = false;
    uint2 rec = g_edata8[beg];
    for (int i = beg; i < end; i++) {
        uint2 cur = rec;
        if (i + 1 < end) rec = g_edata8[i + 1];
        while (i >= nxt) {
            if (dirty) {
                red4(&g_gat[(size_t)n * 64 + 4 * l], ag.x, ag.y, ag.z, ag.w);
                red4(&g_gcn[(size_t)n * 64 + 4 * l], ac.x, ac.y, ac.z, ac.w);
                if (l == 0) red1(&g_den[n], den);
                ag = make_float4(0.f, 0.f, 0.f, 0.f);
                ac = make_float4(0.f, 0.f, 0.f, 0.f);
                den = 0.f;
                dirty = false;
            }
            n++;
            nxt = g_startx[n + 1];
        }
        __half2 p; *reinterpret_cast<unsigned int*>(&p) = cur.y;
        float2 exw = __half22float2(p);
        if (exw.x == 0.f && exw.y == 0.f) continue;
        int s = (int)cur.x;
        float diss = __ldg(&g_dis[s]);
        float ewd = exw.y * diss;
        const __half2* pl = &g_xl_h[(size_t)s * 32 + 2 * l];
        float2 f0 = __half22float2(pl[0]), f1 = __half22float2(pl[1]);
        ag.x += exw.x * f0.x; ag.y += exw.x * f0.y;
        ag.z += exw.x * f1.x; ag.w += exw.x * f1.y;
        const __half2* pg = &g_xg_h[(size_t)s * 32 + 2 * l];
        float2 u0 = __half22float2(pg[0]), u1 = __half22float2(pg[1]);
        ac.x += ewd * u0.x; ac.y += ewd * u0.y;
        ac.z += ewd * u1.x; ac.w += ewd * u1.y;
        den += exw.x;
        dirty = true;
    }
    if (dirty) {
        red4(&g_gat[(size_t)n * 64 + 4 * l], ag.x, ag.y, ag.z, ag.w);
        red4(&g_gcn[(size_t)n * 64 + 4 * l], ac.x, ac.y, ac.z, ac.w);
        if (l == 0) red1(&g_den[n], den);
    }
}

// ---------------- fusion (K-split x2): finalize both branches inline -------------
__global__ void __launch_bounds__(256, 4)
k_fusion(const float* __restrict__ W1, const float* __restrict__ b1,
         const float* __restrict__ w2, const float* __restrict__ b2,
         const float* __restrict__ gat_b, const float* __restrict__ gcn_b,
         float* __restrict__ out, int nrows) {
    extern __shared__ float sm[];
    float (*Xs)[132] = (float(*)[132])sm;
    float (*Ws)[68]  = (float(*)[68])(sm + 64 * 132);
    int tid = threadIdx.x;
    int r0 = blockIdx.x * 128;
    int ty = tid >> 4, tx = tid & 15;
    int n0 = ty * 8, h0 = tx * 4;
    float acc[8][4] = {};

#pragma unroll
    for (int p = 0; p < 2; p++) {
        if (p) __syncthreads();
        {
            int h = tid & 63, kq = (tid >> 6) * 16;
            const float4* src = (const float4*)(W1 + (size_t)h * 128 + p * 64 + kq);
#pragma unroll
            for (int j = 0; j < 4; j++) {
                float4 v = src[j];
                int k = kq + 4 * j;
                Ws[k + 0][h] = v.x; Ws[k + 1][h] = v.y;
                Ws[k + 2][h] = v.z; Ws[k + 3][h] = v.w;
            }
        }
        {
            int r = tid & 127, ko = (tid >> 7) * 32;
            int rr = r0 + r;
            if (rr < nrows) {
                if (p == 0) {
                    float inv = 1.f / g_den[rr];
                    float exs = g_exself[rr];
                    const float4*  pa = (const float4*)(g_gat + (size_t)rr * 64) + (ko >> 2);
                    const __half2* px = &g_xl_h[(size_t)rr * 32 + (ko >> 1)];
                    const float4*  pb = (const float4*)gat_b + (ko >> 2);
#pragma unroll
                    for (int j = 0; j < 8; j++) {
                        float4 a = pa[j], b = pb[j];
                        float2 x0 = __half22float2(px[2 * j]);
                        float2 x1 = __half22float2(px[2 * j + 1]);
                        int k = ko + 4 * j;
                        Xs[k + 0][r] = elu1((a.x + exs * x0.x) * inv + b.x);
                        Xs[k + 1][r] = elu1((a.y + exs * x0.y) * inv + b.y);
                        Xs[k + 2][r] = elu1((a.z + exs * x1.x) * inv + b.z);
                        Xs[k + 3][r] = elu1((a.w + exs * x1.y) * inv + b.w);
                    }
                } else {
                    float dis = g_dis[rr];
                    const float4*  pa = (const float4*)(g_gcn + (size_t)rr * 64) + (ko >> 2);
                    const __half2* px = &g_xg_h[(size_t)rr * 32 + (ko >> 1)];
                    const float4*  pb = (const float4*)gcn_b + (ko >> 2);
#pragma unroll
                    for (int j = 0; j < 8; j++) {
                        float4 a = pa[j], b = pb[j];
                        float2 x0 = __half22float2(px[2 * j]);
                        float2 x1 = __half22float2(px[2 * j + 1]);
                        int k = ko + 4 * j;
                        Xs[k + 0][r] = fmaxf(dis * (a.x + dis * x0.x) + b.x, 0.f);
                        Xs[k + 1][r] = fmaxf(dis * (a.y + dis * x0.y) + b.y, 0.f);
                        Xs[k + 2][r] = fmaxf(dis * (a.z + dis * x1.x) + b.z, 0.f);
                        Xs[k + 3][r] = fmaxf(dis * (a.w + dis * x1.y) + b.w, 0.f);
                    }
                }
            } else {
#pragma unroll
                for (int j = 0; j < 32; j++) Xs[ko + j][r] = 0.f;
            }
        }
        __syncthreads();
#pragma unroll 4
        for (int k = 0; k < 64; k++) {
            float4 x0 = *(const float4*)&Xs[k][n0];
            float4 x1 = *(const float4*)&Xs[k][n0 + 4];
            float4 wv = *(const float4*)&Ws[k][h0];
            float xs[8] = {x0.x, x0.y, x0.z, x0.w, x1.x, x1.y, x1.z, x1.w};
            float ws[4] = {wv.x, wv.y, wv.z, wv.w};
#pragma unroll
            for (int i = 0; i < 8; i++)
#pragma unroll
                for (int j = 0; j < 4; j++) acc[i][j] += xs[i] * ws[j];
        }
    }

    float b1v[4], w2v[4];
#pragma unroll
    for (int j = 0; j < 4; j++) { b1v[j] = b1[h0 + j]; w2v[j] = w2[h0 + j]; }
    float part[8];
#pragma unroll
    for (int i = 0; i < 8; i++) {
        float p = 0.f;
#pragma unroll
        for (int j = 0; j < 4; j++) p += fmaxf(acc[i][j] + b1v[j], 0.f) * w2v[j];
        part[i] = p;
    }
#pragma unroll
    for (int off = 8; off >= 1; off >>= 1)
#pragma unroll
        for (int i = 0; i < 8; i++) part[i] += __shfl_down_sync(0xffffffffu, part[i], off, 16);
    if (tx == 0) {
        float bb = b2[0];
#pragma unroll
        for (int i = 0; i < 8; i++) {
            int r = r0 + n0 + i;
            if (r < nrows) out[r] = part[i] + bb;
        }
    }
}

// ---------------- launch (stream-forked DAG; handles destroyed before return) ----
extern "C" void kernel_launch(void* const* d_in, const int* in_sizes, int n_in,
                              void* d_out, int out_size) {
    const float* x_local  = (const float*)d_in[0];
    const float* x_global = (const float*)d_in[1];
    const float* nf       = (const float*)d_in[2];
    const float* coord    = (const float*)d_in[3];
    const int*   ei       = (const int*)d_in[4];
    const float* fc1w     = (const float*)d_in[5];
    const float* fc1b     = (const float*)d_in[6];
    const float* fc2w     = (const float*)d_in[7];
    const float* fc2b     = (const float*)d_in[8];
    const float* gat_w    = (const float*)d_in[9];
    const float* att_s    = (const float*)d_in[10];
    const float* att_d    = (const float*)d_in[11];
    const float* gat_b    = (const float*)d_in[12];
    const float* gcn_w    = (const float*)d_in[13];
    const float* gcn_b    = (const float*)d_in[14];
    const float* fus_w1   = (const float*)d_in[15];
    const float* fus_b1   = (const float*)d_in[16];
    const float* fus_w2   = (const float*)d_in[17];
    const float* fus_b2   = (const float*)d_in[18];
    float* out = (float*)d_out;

    const int SMEM_MMA = (256 * XS + 128 * XS) * (int)sizeof(__half);  // 104448
    const int SMEM_F   = (64 * 132 + 64 * 68) * (int)sizeof(float);    // 51200
    cudaFuncSetAttribute(k_gemm,   cudaFuncAttributeMaxDynamicSharedMemorySize, SMEM_MMA);
    cudaFuncSetAttribute(k_fusion, cudaFuncAttributeMaxDynamicSharedMemorySize, SMEM_F);

    float *pgat, *pgcn;
    __half2 *pxlh, *pxgh;
    void *pcnt;
    cudaGetSymbolAddress((void**)&pxlh, g_xl_h);
    cudaGetSymbolAddress((void**)&pxgh, g_xg_h);
    cudaGetSymbolAddress((void**)&pgat, g_gat);
    cudaGetSymbolAddress((void**)&pgcn, g_gcn);
    cudaGetSymbolAddress(&pcnt, g_cnt);

    const int NB_N   = (NN + 255) / 256;                 // 196
    const int NB_E   = (EE + 255) / 256;                 // 6250
    const int NB_G   = (NN + 127) / 128;                 // 391
    const int NSCAN  = (NN + 1023) / 1024;               // 49
    const int NGROUP = (EE + RCHUNK - 1) / RCHUNK;       // 25000
    const int NB_R   = (NGROUP * 16 + 255) / 256;        // 1563

    cudaStream_t s1, s2;
    cudaStreamCreateWithFlags(&s1, cudaStreamNonBlocking);
    cudaStreamCreateWithFlags(&s2, cudaStreamNonBlocking);
    cudaEvent_t evRoot, evScan, evMset;
    cudaEventCreateWithFlags(&evRoot, cudaEventDisableTiming);
    cudaEventCreateWithFlags(&evScan, cudaEventDisableTiming);
    cudaEventCreateWithFlags(&evMset, cudaEventDisableTiming);

    cudaEventRecord(evRoot, 0);

    // branch s1: histogram(+rank) + scan chain
    cudaStreamWaitEvent(s1, evRoot, 0);
    cudaMemsetAsync(pcnt, 0, NN * sizeof(int), s1);
    k_hist<<<NB_E, 256, 0, s1>>>(ei);
    k_scan1<<<NSCAN, 256, 0, s1>>>();
    k_scan2<<<1, 1, 0, s1>>>(NSCAN);
    k_scan3<<<NB_N, 256, 0, s1>>>();
    cudaEventRecord(evScan, s1);

    // branch s2: accumulator memsets
    cudaStreamWaitEvent(s2, evRoot, 0);
    cudaMemsetAsync(pgat, 0, (size_t)NN * 64 * sizeof(float), s2);
    cudaMemsetAsync(pgcn, 0, (size_t)NN * 64 * sizeof(float), s2);
    cudaEventRecord(evMset, s2);

    // main stream: node MLP + merged GEMM
    k_nind<<<NB_N, 256>>>(nf, coord, fc1w, fc1b, fc2w, fc2b);
    k_gemm<<<dim3(NB_G, 2), 256, SMEM_MMA>>>(x_local, gat_w, pxlh,
                                             x_global, gcn_w, pxgh,
                                             att_s, att_d, NN);

    // join: bin needs scan + nind + gemm; reduce additionally needs memsets
    cudaStreamWaitEvent(0, evScan, 0);
    k_bin<<<NB_E, 256>>>(ei);
    k_dis<<<NB_N, 256>>>();
    cudaStreamWaitEvent(0, evMset, 0);
    k_reduce<<<NB_R, 256>>>();
    k_fusion<<<NB_G, 256, SMEM_F>>>(fus_w1, fus_b1, fus_w2, fus_b2, gat_b, gcn_b, out, NN);

    cudaStreamDestroy(s1);
    cudaStreamDestroy(s2);
    cudaEventDestroy(evRoot);
    cudaEventDestroy(evScan);
    cudaEventDestroy(evMset);
}